// round 14
// baseline (speedup 1.0000x reference)
#include <cuda_runtime.h>
#include <cuda_fp16.h>
#include <math.h>

#define EPSV 1e-7f

// ---- problem sizes (fixed by the dataset) ----
#define NB 4
#define H0 256
#define W0 448
#define HW0 (H0*W0)      // 114688
#define H1 128
#define W1 224
#define HW1 (H1*W1)      // 28672
#define H2 64
#define W2 112
#define HW2 (H2*W2)      // 7168
#define C0 32
#define C1 64
#define C2 96

// NHWC accumulator pixel strides in u32 units:
//   [0 .. C/2)  : C channels as f16x2
//   [C/2]       : den  (f32)
//   [C/2+1]     : hole (f32)
//   padded to a multiple of 4 u32 (16B) for v4 RED alignment
#define S0 20
#define S1 36
#define S2 52
#define SF 4             // flow acc: 4 f32 (vx, vy, den, pad)

// ---- scratch layout (u32 units) ----
#define OFF_ACC0  0
#define OFF_ACC1  (OFF_ACC0 + NB*HW0*S0)
#define OFF_ACC2  (OFF_ACC1 + NB*HW1*S1)
#define OFF_ACCF  (OFF_ACC2 + NB*HW2*S2)
#define OFF_FLOW1 (OFF_ACCF + NB*HW0*SF)
#define OFF_MET1  (OFF_FLOW1 + NB*2*HW1)
#define OFF_FLOW2 (OFF_MET1 + NB*HW1)
#define OFF_MET2  (OFF_FLOW2 + NB*2*HW2)
#define SCRATCH_TOTAL (OFF_MET2 + NB*HW2)
#define ACC_TOTAL OFF_FLOW1

__device__ __align__(256) unsigned g_scratch[SCRATCH_TOTAL];

__device__ __forceinline__ void red_add_v4_f32(float* p, float a, float b, float c, float d) {
    asm volatile("red.global.add.v4.f32 [%0], {%1,%2,%3,%4};"
                 :: "l"(p), "f"(a), "f"(b), "f"(c), "f"(d) : "memory");
}
__device__ __forceinline__ void red_add_v2_f32(float* p, float a, float b) {
    asm volatile("red.global.add.v2.f32 [%0], {%1,%2};"
                 :: "l"(p), "f"(a), "f"(b) : "memory");
}
__device__ __forceinline__ void red_add_v4_h2(unsigned* p, unsigned a, unsigned b,
                                              unsigned c, unsigned d) {
    asm volatile("red.global.add.noftz.v4.f16x2 [%0], {%1,%2,%3,%4};"
                 :: "l"(p), "r"(a), "r"(b), "r"(c), "r"(d) : "memory");
}
__device__ __forceinline__ unsigned pack_h2(float lo, float hi) {
    __half2 h = __floats2half2_rn(lo, hi);
    return *reinterpret_cast<unsigned*>(&h);
}

// ---- 2x antialiased bilinear downsample body (one stage) ----
template<int Hi, int Wi>
__device__ __forceinline__ void resize_body(
    int i,
    const float* __restrict__ src_flow,
    const float* __restrict__ src_met,
    float* __restrict__ dst_flow,
    float* __restrict__ dst_met,
    float flow_scale)
{
    const int Ho = Hi / 2, Wo = Wi / 2;
    int total = NB * 3 * Ho * Wo;
    if (i >= total) return;
    int p  = i % (Ho * Wo);
    int nc = i / (Ho * Wo);
    int c  = nc % 3;
    int n  = nc / 3;
    int oy = p / Wo, ox = p % Wo;

    const float raw[4] = {0.25f, 0.75f, 0.75f, 0.25f};
    float wy[4], wx[4];
    int   jy[4], jx[4];
    float sy = 0.f, sx = 0.f;
#pragma unroll
    for (int k = 0; k < 4; k++) {
        int j = 2 * oy - 1 + k;
        float w = (j >= 0 && j < Hi) ? raw[k] : 0.f;
        jy[k] = min(max(j, 0), Hi - 1);
        wy[k] = w; sy += w;
    }
#pragma unroll
    for (int k = 0; k < 4; k++) {
        int j = 2 * ox - 1 + k;
        float w = (j >= 0 && j < Wi) ? raw[k] : 0.f;
        jx[k] = min(max(j, 0), Wi - 1);
        wx[k] = w; sx += w;
    }
    float inv = 1.f / (sy * sx);

    const float* src = (c < 2) ? (src_flow + ((size_t)n * 2 + c) * Hi * Wi)
                               : (src_met  + (size_t)n * Hi * Wi);
    float acc = 0.f;
#pragma unroll
    for (int ky = 0; ky < 4; ky++) {
        if (wy[ky] == 0.f) continue;
        const float* row = src + (size_t)jy[ky] * Wi;
        float a = 0.f;
#pragma unroll
        for (int kx = 0; kx < 4; kx++) a += wx[kx] * row[jx[kx]];
        acc += wy[ky] * a;
    }
    acc *= inv;

    if (c < 2) dst_flow[((size_t)n * 2 + c) * Ho * Wo + p] = acc * flow_scale;
    else       dst_met [(size_t)n * Ho * Wo + p] = acc;
}

// evaluate the level-1 (half-res) antialiased resample of src[H0][W0] at (oy,ox)
__device__ float resize_sample_l1(const float* __restrict__ src, int oy, int ox)
{
    const float raw[4] = {0.25f, 0.75f, 0.75f, 0.25f};
    float wy[4], wx[4];
    int   jy[4], jx[4];
    float sy = 0.f, sx = 0.f;
#pragma unroll
    for (int k = 0; k < 4; k++) {
        int j = 2 * oy - 1 + k;
        float w = (j >= 0 && j < H0) ? raw[k] : 0.f;
        jy[k] = min(max(j, 0), H0 - 1);
        wy[k] = w; sy += w;
    }
#pragma unroll
    for (int k = 0; k < 4; k++) {
        int j = 2 * ox - 1 + k;
        float w = (j >= 0 && j < W0) ? raw[k] : 0.f;
        jx[k] = min(max(j, 0), W0 - 1);
        wx[k] = w; sx += w;
    }
    float acc = 0.f;
#pragma unroll
    for (int ky = 0; ky < 4; ky++) {
        if (wy[ky] == 0.f) continue;
        const float* row = src + (size_t)jy[ky] * W0;
        float a = 0.f;
#pragma unroll
        for (int kx = 0; kx < 4; kx++) a += wx[kx] * row[jx[kx]];
        acc += wy[ky] * a;
    }
    return acc / (sy * sx);
}

// level-2 resize composed directly from level-0 (bit-identical to 2-pass:
// scales are exact powers of two; tap/renorm logic matches per stage)
__device__ __forceinline__ void resize2_composed_body(
    int i,
    const float* __restrict__ F12,
    const float* __restrict__ m1t,
    float* __restrict__ dst_flow2,
    float* __restrict__ dst_met2)
{
    int total = NB * 3 * HW2;
    if (i >= total) return;
    int p  = i % HW2;
    int nc = i / HW2;
    int c  = nc % 3;
    int n  = nc / 3;
    int oy = p / W2, ox = p % W2;

    const float raw[4] = {0.25f, 0.75f, 0.75f, 0.25f};
    float wy[4], wx[4];
    int   jy[4], jx[4];
    float sy = 0.f, sx = 0.f;
#pragma unroll
    for (int k = 0; k < 4; k++) {
        int j = 2 * oy - 1 + k;
        float w = (j >= 0 && j < H1) ? raw[k] : 0.f;
        jy[k] = min(max(j, 0), H1 - 1);
        wy[k] = w; sy += w;
    }
#pragma unroll
    for (int k = 0; k < 4; k++) {
        int j = 2 * ox - 1 + k;
        float w = (j >= 0 && j < W1) ? raw[k] : 0.f;
        jx[k] = min(max(j, 0), W1 - 1);
        wx[k] = w; sx += w;
    }
    float inv = 1.f / (sy * sx);

    const float* src = (c < 2) ? (F12 + ((size_t)n * 2 + c) * HW0)
                               : (m1t + (size_t)n * HW0);
    float acc = 0.f;
    for (int ky = 0; ky < 4; ky++) {
        if (wy[ky] == 0.f) continue;
        float a = 0.f;
        for (int kx = 0; kx < 4; kx++) {
            if (wx[kx] == 0.f) continue;
            a += wx[kx] * resize_sample_l1(src, jy[ky], jx[kx]);
        }
        acc += wy[ky] * a;
    }
    acc *= inv;

    if (c < 2) dst_flow2[((size_t)n * 2 + c) * HW2 + p] = acc * 0.125f;
    else       dst_met2 [(size_t)n * HW2 + p] = acc;
}

// ---- prep: resize1 + composed-resize2 + accumulator zeroing, ONE launch ----
#define NBLK_R1  ((NB*3*HW1 + 255) / 256)   // 1344
#define NBLK_R2C ((NB*3*HW2 + 255) / 256)   // 336
#define NBLK_Z   2048
#define NVEC_ACC (ACC_TOTAL / 4)

__global__ __launch_bounds__(256) void prep_kernel(
    const float* __restrict__ F12,
    const float* __restrict__ m1t,
    float* __restrict__ flow1, float* __restrict__ met1,
    float* __restrict__ flow2, float* __restrict__ met2,
    unsigned* __restrict__ scratch)
{
    int b = blockIdx.x;
    if (b < NBLK_R1) {
        resize_body<H0, W0>(b * 256 + threadIdx.x, F12, m1t,
                            flow1, met1, 0.25f);
    } else if (b < NBLK_R1 + NBLK_R2C) {
        resize2_composed_body((b - NBLK_R1) * 256 + threadIdx.x,
                              F12, m1t, flow2, met2);
    } else {
        uint4* dst = reinterpret_cast<uint4*>(scratch);
        const uint4 z = make_uint4(0u, 0u, 0u, 0u);
        int tid = (b - NBLK_R1 - NBLK_R2C) * 256 + threadIdx.x;
        const int stride = NBLK_Z * 256;
        for (int j = tid; j < NVEC_ACC; j += stride) dst[j] = z;
    }
}

// ---- splat bodies ----
template<int C, int H, int W, int SP>
__device__ __forceinline__ void splat_level_body(
    int i,
    const float* __restrict__ feat,
    const float* __restrict__ flow,
    const float* __restrict__ metric,
    unsigned* __restrict__ acc,
    float flow_scale)
{
    constexpr int P = NB * H * W;
    int pix = i % P;
    int g   = i / P;
    int n = pix / (H * W);
    int p = pix % (H * W);
    int y = p / W, x = p % W;

    const float* fl = flow + (size_t)n * 2 * H * W;
    float gx = (float)x + fl[p]         * flow_scale;
    float gy = (float)y + fl[H * W + p] * flow_scale;
    float x0f = floorf(gx), y0f = floorf(gy);
    float fx = gx - x0f, fy = gy - y0f;
    int x0 = (int)x0f, y0 = (int)y0f;

    float m = metric[(size_t)n * H * W + p];
    float e = __expf(fminf(fmaxf(-m, -20.f), 20.f));

    float w[4]  = {(1.f - fx) * (1.f - fy), fx * (1.f - fy),
                   (1.f - fx) * fy,         fx * fy};
    int   xi[2] = {x0, x0 + 1};
    int   yi[2] = {y0, y0 + 1};
    bool  vx[2] = {x0 >= 0 && x0 < W, x0 + 1 >= 0 && x0 + 1 < W};
    bool  vy[2] = {y0 >= 0 && y0 < H, y0 + 1 >= 0 && y0 + 1 < H};

    int c0 = g * 16;
    const float* fp = feat + (size_t)n * C * H * W + (size_t)c0 * H * W + p;
    float v[16];
#pragma unroll
    for (int j = 0; j < 16; j++) v[j] = fp[(size_t)j * H * W] * e;

#pragma unroll
    for (int ky = 0; ky < 2; ky++) {
#pragma unroll
        for (int kx = 0; kx < 2; kx++) {
            if (!(vx[kx] && vy[ky])) continue;
            float wk = w[ky * 2 + kx];
            unsigned* pixbase = acc + ((size_t)n * H * W + yi[ky] * W + xi[kx]) * SP;
            unsigned pk[8];
#pragma unroll
            for (int j = 0; j < 8; j++)
                pk[j] = pack_h2(wk * v[2 * j], wk * v[2 * j + 1]);
            unsigned* fb = pixbase + (c0 >> 1);
            red_add_v4_h2(fb,     pk[0], pk[1], pk[2], pk[3]);
            red_add_v4_h2(fb + 4, pk[4], pk[5], pk[6], pk[7]);
            if (g == 0)
                red_add_v2_f32(reinterpret_cast<float*>(pixbase + (C >> 1)),
                               wk * e, wk);
        }
    }
}

__device__ __forceinline__ void splat_flow_body(
    int i,
    const float* __restrict__ F21,
    const float* __restrict__ m2t,
    float* __restrict__ acc)
{
    constexpr int H = H0, W = W0;
    int n = i / (H * W);
    int p = i % (H * W);
    int y = p / W, x = p % W;

    const float* fl = F21 + (size_t)n * 2 * H * W;
    float ux = fl[p] * 0.5f;
    float uy = fl[H * W + p] * 0.5f;
    float gx = (float)x + ux;
    float gy = (float)y + uy;
    float x0f = floorf(gx), y0f = floorf(gy);
    float fx = gx - x0f, fy = gy - y0f;
    int x0 = (int)x0f, y0 = (int)y0f;

    float m = m2t[(size_t)n * H * W + p];
    float e = __expf(fminf(fmaxf(-m, -20.f), 20.f));
    float vx0 = ux * e, vy0 = uy * e;

    float w[4]  = {(1.f - fx) * (1.f - fy), fx * (1.f - fy),
                   (1.f - fx) * fy,         fx * fy};
    int   xi[2] = {x0, x0 + 1};
    int   yi[2] = {y0, y0 + 1};
    bool  bx[2] = {x0 >= 0 && x0 < W, x0 + 1 >= 0 && x0 + 1 < W};
    bool  by[2] = {y0 >= 0 && y0 < H, y0 + 1 >= 0 && y0 + 1 < H};

#pragma unroll
    for (int ky = 0; ky < 2; ky++) {
#pragma unroll
        for (int kx = 0; kx < 2; kx++) {
            if (!(bx[kx] && by[ky])) continue;
            float wk = w[ky * 2 + kx];
            float* base = acc + ((size_t)n * H * W + yi[ky] * W + xi[kx]) * SF;
            red_add_v4_f32(base, wk * vx0, wk * vy0, wk * e, 0.f);
        }
    }
}

// ---- one fused splat kernel: block-range dispatch (largest first) ----
#define NBLK_S0 (NB*HW0*(C0/16)/256)   // 3584
#define NBLK_SF (NB*HW0/256)           // 1792
#define NBLK_S1 (NB*HW1*(C1/16)/256)   // 1792
#define NBLK_S2 (NB*HW2*(C2/16)/256)   // 672
#define NBLK_SPLAT (NBLK_S0+NBLK_SF+NBLK_S1+NBLK_S2)

__global__ __launch_bounds__(256) void splat_fused_kernel(
    const float* __restrict__ x1_0, const float* __restrict__ x1_1,
    const float* __restrict__ x1_2,
    const float* __restrict__ m1t,  const float* __restrict__ m2t,
    const float* __restrict__ F12,  const float* __restrict__ F21,
    const float* __restrict__ flow1, const float* __restrict__ met1,
    const float* __restrict__ flow2, const float* __restrict__ met2,
    unsigned* __restrict__ acc0, unsigned* __restrict__ acc1,
    unsigned* __restrict__ acc2, float* __restrict__ accF)
{
    int b = blockIdx.x;
    if (b < NBLK_S0) {
        int i = b * 256 + threadIdx.x;
        splat_level_body<C0, H0, W0, S0>(i, x1_0, F12, m1t, acc0, 0.5f);
    } else if (b < NBLK_S0 + NBLK_SF) {
        int i = (b - NBLK_S0) * 256 + threadIdx.x;
        splat_flow_body(i, F21, m2t, accF);
    } else if (b < NBLK_S0 + NBLK_SF + NBLK_S1) {
        int i = (b - NBLK_S0 - NBLK_SF) * 256 + threadIdx.x;
        splat_level_body<C1, H1, W1, S1>(i, x1_1, flow1, met1, acc1, 1.0f);
    } else {
        int i = (b - NBLK_S0 - NBLK_SF - NBLK_S1) * 256 + threadIdx.x;
        splat_level_body<C2, H2, W2, S2>(i, x1_2, flow2, met2, acc2, 1.0f);
    }
}

// ---- norm bodies (smem provided by caller; sized for the largest user) ----
template<int C, int H, int W, int SP, int TP>
__device__ __forceinline__ void norm_level_body(
    int blk,
    const unsigned* __restrict__ acc,
    float* __restrict__ out,
    float* __restrict__ bm,
    unsigned* tile, float* inv)
{
    constexpr int SPAD = SP + 1;
    int gp0 = blk * TP;
    const uint4* src4 = reinterpret_cast<const uint4*>(acc + (size_t)gp0 * SP);
    constexpr int NV = TP * SP / 4;
    for (int j4 = threadIdx.x; j4 < NV; j4 += 256) {
        uint4 val = src4[j4];
        int j  = j4 * 4;
        int pl = j / SP;
        int k  = j - pl * SP;
        unsigned* t = tile + pl * SPAD + k;
        t[0] = val.x; t[1] = val.y; t[2] = val.z; t[3] = val.w;
    }
    __syncthreads();
    if (threadIdx.x < TP)
        inv[threadIdx.x] =
            1.f / (__uint_as_float(tile[threadIdx.x * SPAD + (C >> 1)]) + EPSV);
    __syncthreads();

    int n  = gp0 / (H * W);
    int p0 = gp0 % (H * W);
    float* outn = out + (size_t)n * C * H * W;
    constexpr int NQ = TP / 4;
    constexpr int NOUT = (C / 2) * NQ;
    for (int j = threadIdx.x; j < NOUT; j += 256) {
        int q  = j % NQ;
        int cp = j / NQ;
        int pl = 4 * q;
        unsigned u0 = tile[(pl + 0) * SPAD + cp];
        unsigned u1 = tile[(pl + 1) * SPAD + cp];
        unsigned u2 = tile[(pl + 2) * SPAD + cp];
        unsigned u3 = tile[(pl + 3) * SPAD + cp];
        __half2 h0 = *reinterpret_cast<__half2*>(&u0);
        __half2 h1 = *reinterpret_cast<__half2*>(&u1);
        __half2 h2 = *reinterpret_cast<__half2*>(&u2);
        __half2 h3 = *reinterpret_cast<__half2*>(&u3);
        float i0 = inv[pl], i1 = inv[pl + 1], i2 = inv[pl + 2], i3 = inv[pl + 3];
        float4 lo = make_float4(__low2float(h0) * i0, __low2float(h1) * i1,
                                __low2float(h2) * i2, __low2float(h3) * i3);
        float4 hi = make_float4(__high2float(h0) * i0, __high2float(h1) * i1,
                                __high2float(h2) * i2, __high2float(h3) * i3);
        float* base = outn + (size_t)(2 * cp) * H * W + p0 + pl;
        *reinterpret_cast<float4*>(base)         = lo;
        *reinterpret_cast<float4*>(base + H * W) = hi;
    }
    if (threadIdx.x < TP) {
        float h = __uint_as_float(tile[threadIdx.x * SPAD + (C >> 1) + 1]);
        float r = h / (h + EPSV);
        bm[(size_t)gp0 + threadIdx.x] = (r <= 0.5f) ? 1.f : 0.f;
    }
}

__device__ __forceinline__ void norm_flow_body(
    int i, const float* __restrict__ acc, float* __restrict__ ft2)
{
    float4 a = *reinterpret_cast<const float4*>(acc + (size_t)i * SF);
    float inv = 1.f / (a.z + EPSV);
    int n = i / HW0;
    int p = i % HW0;
    float* dst = ft2 + (size_t)n * 2 * HW0;
    dst[p]       = -a.x * inv;
    dst[HW0 + p] = -a.y * inv;
}

// ---- ALL normalization in one launch (union smem, largest segment first) ----
#define NBLK_N0 (NB*HW0/64)    // 7168  (TP=64)
#define NBLK_NF (NB*HW0/256)   // 1792
#define NBLK_N1 (NB*HW1/32)    // 3584  (TP=32)
#define NBLK_N2 (NB*HW2/32)    // 896   (TP=32)
#define NBLK_NORM (NBLK_N0+NBLK_NF+NBLK_N1+NBLK_N2)

// union smem: max(64*(S0+1), 32*(S1+1), 32*(S2+1)) = 1696
#define TILE_MAX 1696

__global__ __launch_bounds__(256) void norm_fused_kernel(
    const unsigned* __restrict__ acc0, const unsigned* __restrict__ acc1,
    const unsigned* __restrict__ acc2, const float* __restrict__ accF,
    float* __restrict__ w0, float* __restrict__ w1, float* __restrict__ w2,
    float* __restrict__ bm0, float* __restrict__ bm1, float* __restrict__ bm2,
    float* __restrict__ ft2)
{
    __shared__ unsigned tile[TILE_MAX];
    __shared__ float inv[64];
    int b = blockIdx.x;
    if (b < NBLK_N0) {
        norm_level_body<C0, H0, W0, S0, 64>(b, acc0, w0, bm0, tile, inv);
    } else if (b < NBLK_N0 + NBLK_NF) {
        int i = (b - NBLK_N0) * 256 + threadIdx.x;
        norm_flow_body(i, accF, ft2);
    } else if (b < NBLK_N0 + NBLK_NF + NBLK_N1) {
        norm_level_body<C1, H1, W1, S1, 32>(b - NBLK_N0 - NBLK_NF,
                                            acc1, w1, bm1, tile, inv);
    } else {
        norm_level_body<C2, H2, W2, S2, 32>(b - NBLK_N0 - NBLK_NF - NBLK_N1,
                                            acc2, w2, bm2, tile, inv);
    }
}

extern "C" void kernel_launch(void* const* d_in, const int* in_sizes, int n_in,
                              void* d_out, int out_size)
{
    // metadata order: 0:x1_0 1:x2_0 2:x1_1 3:x2_1 4:x1_2 5:x2_2 6:m1t 7:m2t 8:F12 9:F21
    const float* x1_0 = (const float*)d_in[0];
    const float* x1_1 = (const float*)d_in[2];
    const float* x1_2 = (const float*)d_in[4];
    const float* m1t = (const float*)d_in[6];
    const float* m2t = (const float*)d_in[7];
    const float* F12 = (const float*)d_in[8];
    const float* F21 = (const float*)d_in[9];

    float* out = (float*)d_out;
    float* w0  = out;
    float* w1  = w0 + (size_t)NB * C0 * HW0;
    float* w2  = w1 + (size_t)NB * C1 * HW1;
    float* bm0 = w2 + (size_t)NB * C2 * HW2;
    float* bm1 = bm0 + (size_t)NB * HW0;
    float* bm2 = bm1 + (size_t)NB * HW1;
    float* ft2 = bm2 + (size_t)NB * HW2;

    unsigned* scratch = nullptr;
    cudaGetSymbolAddress((void**)&scratch, g_scratch);
    unsigned* acc0 = scratch + OFF_ACC0;
    unsigned* acc1 = scratch + OFF_ACC1;
    unsigned* acc2 = scratch + OFF_ACC2;
    float* accF  = reinterpret_cast<float*>(scratch + OFF_ACCF);
    float* flow1 = reinterpret_cast<float*>(scratch + OFF_FLOW1);
    float* met1  = reinterpret_cast<float*>(scratch + OFF_MET1);
    float* flow2 = reinterpret_cast<float*>(scratch + OFF_FLOW2);
    float* met2  = reinterpret_cast<float*>(scratch + OFF_MET2);

    const int TB = 256;

    // prep: resize1 + composed-resize2 + zero accumulators, one launch
    prep_kernel<<<NBLK_R1 + NBLK_R2C + NBLK_Z, TB>>>(
        F12, m1t, flow1, met1, flow2, met2, scratch);

    // all splats in one launch (largest segment first for wave packing)
    splat_fused_kernel<<<NBLK_SPLAT, TB>>>(
        x1_0, x1_1, x1_2, m1t, m2t, F12, F21,
        flow1, met1, flow2, met2, acc0, acc1, acc2, accF);

    // ALL normalization in one launch
    norm_fused_kernel<<<NBLK_NORM, TB>>>(
        acc0, acc1, acc2, accF, w0, w1, w2, bm0, bm1, bm2, ft2);
}

// round 15
// speedup vs baseline: 1.0943x; 1.0943x over previous
#include <cuda_runtime.h>
#include <cuda_fp16.h>
#include <math.h>

#define EPSV 1e-7f

// ---- problem sizes (fixed by the dataset) ----
#define NB 4
#define H0 256
#define W0 448
#define HW0 (H0*W0)      // 114688
#define H1 128
#define W1 224
#define HW1 (H1*W1)      // 28672
#define H2 64
#define W2 112
#define HW2 (H2*W2)      // 7168
#define C0 32
#define C1 64
#define C2 96

// NHWC accumulator pixel strides in u32 units:
//   [0 .. C/2)  : C channels as f16x2
//   [C/2]       : den  (f32)
//   [C/2+1]     : hole (f32)
//   padded to a multiple of 4 u32 (16B) for v4 RED alignment
#define S0 20
#define S1 36
#define S2 52
#define SF 4             // flow acc: 4 f32 (vx, vy, den, pad)

// ---- scratch layout (u32 units) ----
#define OFF_ACC0  0
#define OFF_ACC1  (OFF_ACC0 + NB*HW0*S0)
#define OFF_ACC2  (OFF_ACC1 + NB*HW1*S1)
#define OFF_ACCF  (OFF_ACC2 + NB*HW2*S2)
#define OFF_FLOW1 (OFF_ACCF + NB*HW0*SF)
#define OFF_MET1  (OFF_FLOW1 + NB*2*HW1)
#define OFF_FLOW2 (OFF_MET1 + NB*HW1)
#define OFF_MET2  (OFF_FLOW2 + NB*2*HW2)
#define SCRATCH_TOTAL (OFF_MET2 + NB*HW2)
#define ACC_TOTAL OFF_FLOW1

__device__ __align__(256) unsigned g_scratch[SCRATCH_TOTAL];

__device__ __forceinline__ void red_add_v4_f32(float* p, float a, float b, float c, float d) {
    asm volatile("red.global.add.v4.f32 [%0], {%1,%2,%3,%4};"
                 :: "l"(p), "f"(a), "f"(b), "f"(c), "f"(d) : "memory");
}
__device__ __forceinline__ void red_add_v2_f32(float* p, float a, float b) {
    asm volatile("red.global.add.v2.f32 [%0], {%1,%2};"
                 :: "l"(p), "f"(a), "f"(b) : "memory");
}
__device__ __forceinline__ void red_add_v4_h2(unsigned* p, unsigned a, unsigned b,
                                              unsigned c, unsigned d) {
    asm volatile("red.global.add.noftz.v4.f16x2 [%0], {%1,%2,%3,%4};"
                 :: "l"(p), "r"(a), "r"(b), "r"(c), "r"(d) : "memory");
}
__device__ __forceinline__ unsigned pack_h2(float lo, float hi) {
    __half2 h = __floats2half2_rn(lo, hi);
    return *reinterpret_cast<unsigned*>(&h);
}

// ---- 2x antialiased bilinear downsample body ----
template<int Hi, int Wi>
__device__ __forceinline__ void resize_body(
    int i,
    const float* __restrict__ src_flow,
    const float* __restrict__ src_met,
    float* __restrict__ dst_flow,
    float* __restrict__ dst_met,
    float flow_scale)
{
    const int Ho = Hi / 2, Wo = Wi / 2;
    int total = NB * 3 * Ho * Wo;
    if (i >= total) return;
    int p  = i % (Ho * Wo);
    int nc = i / (Ho * Wo);
    int c  = nc % 3;
    int n  = nc / 3;
    int oy = p / Wo, ox = p % Wo;

    const float raw[4] = {0.25f, 0.75f, 0.75f, 0.25f};
    float wy[4], wx[4];
    int   jy[4], jx[4];
    float sy = 0.f, sx = 0.f;
#pragma unroll
    for (int k = 0; k < 4; k++) {
        int j = 2 * oy - 1 + k;
        float w = (j >= 0 && j < Hi) ? raw[k] : 0.f;
        jy[k] = min(max(j, 0), Hi - 1);
        wy[k] = w; sy += w;
    }
#pragma unroll
    for (int k = 0; k < 4; k++) {
        int j = 2 * ox - 1 + k;
        float w = (j >= 0 && j < Wi) ? raw[k] : 0.f;
        jx[k] = min(max(j, 0), Wi - 1);
        wx[k] = w; sx += w;
    }
    float inv = 1.f / (sy * sx);

    const float* src = (c < 2) ? (src_flow + ((size_t)n * 2 + c) * Hi * Wi)
                               : (src_met  + (size_t)n * Hi * Wi);
    float acc = 0.f;
#pragma unroll
    for (int ky = 0; ky < 4; ky++) {
        if (wy[ky] == 0.f) continue;
        const float* row = src + (size_t)jy[ky] * Wi;
        float a = 0.f;
#pragma unroll
        for (int kx = 0; kx < 4; kx++) a += wx[kx] * row[jx[kx]];
        acc += wy[ky] * a;
    }
    acc *= inv;

    if (c < 2) dst_flow[((size_t)n * 2 + c) * Ho * Wo + p] = acc * flow_scale;
    else       dst_met [(size_t)n * Ho * Wo + p] = acc;
}

// ---- resize level1 + accumulator zeroing fused into ONE launch ----
#define NBLK_R1 ((NB*3*HW1 + 255) / 256)    // 1344
#define NBLK_Z  2048
#define NVEC_ACC (ACC_TOTAL / 4)            // uint4 count (ACC_TOTAL % 4 == 0)

__global__ __launch_bounds__(256) void resize1_zero_kernel(
    const float* __restrict__ F12,
    const float* __restrict__ m1t,
    float* __restrict__ dst_flow,
    float* __restrict__ dst_met,
    unsigned* __restrict__ scratch)
{
    int b = blockIdx.x;
    if (b < NBLK_R1) {
        resize_body<H0, W0>(b * 256 + threadIdx.x, F12, m1t,
                            dst_flow, dst_met, 0.25f);
    } else {
        uint4* dst = reinterpret_cast<uint4*>(scratch);
        const uint4 z = make_uint4(0u, 0u, 0u, 0u);
        int tid = (b - NBLK_R1) * 256 + threadIdx.x;
        const int stride = NBLK_Z * 256;
        for (int j = tid; j < NVEC_ACC; j += stride) dst[j] = z;
    }
}

__global__ __launch_bounds__(256) void resize2_kernel(
    const float* __restrict__ src_flow,
    const float* __restrict__ src_met,
    float* __restrict__ dst_flow,
    float* __restrict__ dst_met)
{
    resize_body<H1, W1>(blockIdx.x * 256 + threadIdx.x, src_flow, src_met,
                        dst_flow, dst_met, 0.5f);
}

// ---- splat bodies ----
template<int C, int H, int W, int SP>
__device__ __forceinline__ void splat_level_body(
    int i,
    const float* __restrict__ feat,
    const float* __restrict__ flow,
    const float* __restrict__ metric,
    unsigned* __restrict__ acc,
    float flow_scale)
{
    constexpr int P = NB * H * W;
    int pix = i % P;
    int g   = i / P;
    int n = pix / (H * W);
    int p = pix % (H * W);
    int y = p / W, x = p % W;

    const float* fl = flow + (size_t)n * 2 * H * W;
    float gx = (float)x + fl[p]         * flow_scale;
    float gy = (float)y + fl[H * W + p] * flow_scale;
    float x0f = floorf(gx), y0f = floorf(gy);
    float fx = gx - x0f, fy = gy - y0f;
    int x0 = (int)x0f, y0 = (int)y0f;

    float m = metric[(size_t)n * H * W + p];
    float e = __expf(fminf(fmaxf(-m, -20.f), 20.f));

    float w[4]  = {(1.f - fx) * (1.f - fy), fx * (1.f - fy),
                   (1.f - fx) * fy,         fx * fy};
    int   xi[2] = {x0, x0 + 1};
    int   yi[2] = {y0, y0 + 1};
    bool  vx[2] = {x0 >= 0 && x0 < W, x0 + 1 >= 0 && x0 + 1 < W};
    bool  vy[2] = {y0 >= 0 && y0 < H, y0 + 1 >= 0 && y0 + 1 < H};

    int c0 = g * 16;
    const float* fp = feat + (size_t)n * C * H * W + (size_t)c0 * H * W + p;
    float v[16];
#pragma unroll
    for (int j = 0; j < 16; j++) v[j] = fp[(size_t)j * H * W] * e;

#pragma unroll
    for (int ky = 0; ky < 2; ky++) {
#pragma unroll
        for (int kx = 0; kx < 2; kx++) {
            if (!(vx[kx] && vy[ky])) continue;
            float wk = w[ky * 2 + kx];
            unsigned* pixbase = acc + ((size_t)n * H * W + yi[ky] * W + xi[kx]) * SP;
            unsigned pk[8];
#pragma unroll
            for (int j = 0; j < 8; j++)
                pk[j] = pack_h2(wk * v[2 * j], wk * v[2 * j + 1]);
            unsigned* fb = pixbase + (c0 >> 1);
            red_add_v4_h2(fb,     pk[0], pk[1], pk[2], pk[3]);
            red_add_v4_h2(fb + 4, pk[4], pk[5], pk[6], pk[7]);
            if (g == 0)
                red_add_v2_f32(reinterpret_cast<float*>(pixbase + (C >> 1)),
                               wk * e, wk);
        }
    }
}

__device__ __forceinline__ void splat_flow_body(
    int i,
    const float* __restrict__ F21,
    const float* __restrict__ m2t,
    float* __restrict__ acc)
{
    constexpr int H = H0, W = W0;
    int n = i / (H * W);
    int p = i % (H * W);
    int y = p / W, x = p % W;

    const float* fl = F21 + (size_t)n * 2 * H * W;
    float ux = fl[p] * 0.5f;
    float uy = fl[H * W + p] * 0.5f;
    float gx = (float)x + ux;
    float gy = (float)y + uy;
    float x0f = floorf(gx), y0f = floorf(gy);
    float fx = gx - x0f, fy = gy - y0f;
    int x0 = (int)x0f, y0 = (int)y0f;

    float m = m2t[(size_t)n * H * W + p];
    float e = __expf(fminf(fmaxf(-m, -20.f), 20.f));
    float vx0 = ux * e, vy0 = uy * e;

    float w[4]  = {(1.f - fx) * (1.f - fy), fx * (1.f - fy),
                   (1.f - fx) * fy,         fx * fy};
    int   xi[2] = {x0, x0 + 1};
    int   yi[2] = {y0, y0 + 1};
    bool  bx[2] = {x0 >= 0 && x0 < W, x0 + 1 >= 0 && x0 + 1 < W};
    bool  by[2] = {y0 >= 0 && y0 < H, y0 + 1 >= 0 && y0 + 1 < H};

#pragma unroll
    for (int ky = 0; ky < 2; ky++) {
#pragma unroll
        for (int kx = 0; kx < 2; kx++) {
            if (!(bx[kx] && by[ky])) continue;
            float wk = w[ky * 2 + kx];
            float* base = acc + ((size_t)n * H * W + yi[ky] * W + xi[kx]) * SF;
            red_add_v4_f32(base, wk * vx0, wk * vy0, wk * e, 0.f);
        }
    }
}

// ---- one fused splat kernel: block-range dispatch (largest first) ----
#define NBLK_S0 (NB*HW0*(C0/16)/256)   // 3584
#define NBLK_SF (NB*HW0/256)           // 1792
#define NBLK_S1 (NB*HW1*(C1/16)/256)   // 1792
#define NBLK_S2 (NB*HW2*(C2/16)/256)   // 672
#define NBLK_SPLAT (NBLK_S0+NBLK_SF+NBLK_S1+NBLK_S2)

__global__ __launch_bounds__(256) void splat_fused_kernel(
    const float* __restrict__ x1_0, const float* __restrict__ x1_1,
    const float* __restrict__ x1_2,
    const float* __restrict__ m1t,  const float* __restrict__ m2t,
    const float* __restrict__ F12,  const float* __restrict__ F21,
    const float* __restrict__ flow1, const float* __restrict__ met1,
    const float* __restrict__ flow2, const float* __restrict__ met2,
    unsigned* __restrict__ acc0, unsigned* __restrict__ acc1,
    unsigned* __restrict__ acc2, float* __restrict__ accF)
{
    int b = blockIdx.x;
    if (b < NBLK_S0) {
        int i = b * 256 + threadIdx.x;
        splat_level_body<C0, H0, W0, S0>(i, x1_0, F12, m1t, acc0, 0.5f);
    } else if (b < NBLK_S0 + NBLK_SF) {
        int i = (b - NBLK_S0) * 256 + threadIdx.x;
        splat_flow_body(i, F21, m2t, accF);
    } else if (b < NBLK_S0 + NBLK_SF + NBLK_S1) {
        int i = (b - NBLK_S0 - NBLK_SF) * 256 + threadIdx.x;
        splat_level_body<C1, H1, W1, S1>(i, x1_1, flow1, met1, acc1, 1.0f);
    } else {
        int i = (b - NBLK_S0 - NBLK_SF - NBLK_S1) * 256 + threadIdx.x;
        splat_level_body<C2, H2, W2, S2>(i, x1_2, flow2, met2, acc2, 1.0f);
    }
}

// ---- norm bodies (smem provided by caller; sized for the largest user) ----
template<int C, int H, int W, int SP, int TP>
__device__ __forceinline__ void norm_level_body(
    int blk,
    const unsigned* __restrict__ acc,
    float* __restrict__ out,
    float* __restrict__ bm,
    unsigned* tile, float* inv)
{
    constexpr int SPAD = SP + 1;
    int gp0 = blk * TP;
    const uint4* src4 = reinterpret_cast<const uint4*>(acc + (size_t)gp0 * SP);
    constexpr int NV = TP * SP / 4;
    for (int j4 = threadIdx.x; j4 < NV; j4 += 256) {
        uint4 val = src4[j4];
        int j  = j4 * 4;
        int pl = j / SP;
        int k  = j - pl * SP;
        unsigned* t = tile + pl * SPAD + k;
        t[0] = val.x; t[1] = val.y; t[2] = val.z; t[3] = val.w;
    }
    __syncthreads();
    if (threadIdx.x < TP)
        inv[threadIdx.x] =
            1.f / (__uint_as_float(tile[threadIdx.x * SPAD + (C >> 1)]) + EPSV);
    __syncthreads();

    int n  = gp0 / (H * W);
    int p0 = gp0 % (H * W);
    float* outn = out + (size_t)n * C * H * W;
    constexpr int NQ = TP / 4;
    constexpr int NOUT = (C / 2) * NQ;
    for (int j = threadIdx.x; j < NOUT; j += 256) {
        int q  = j % NQ;
        int cp = j / NQ;
        int pl = 4 * q;
        unsigned u0 = tile[(pl + 0) * SPAD + cp];
        unsigned u1 = tile[(pl + 1) * SPAD + cp];
        unsigned u2 = tile[(pl + 2) * SPAD + cp];
        unsigned u3 = tile[(pl + 3) * SPAD + cp];
        __half2 h0 = *reinterpret_cast<__half2*>(&u0);
        __half2 h1 = *reinterpret_cast<__half2*>(&u1);
        __half2 h2 = *reinterpret_cast<__half2*>(&u2);
        __half2 h3 = *reinterpret_cast<__half2*>(&u3);
        float i0 = inv[pl], i1 = inv[pl + 1], i2 = inv[pl + 2], i3 = inv[pl + 3];
        float4 lo = make_float4(__low2float(h0) * i0, __low2float(h1) * i1,
                                __low2float(h2) * i2, __low2float(h3) * i3);
        float4 hi = make_float4(__high2float(h0) * i0, __high2float(h1) * i1,
                                __high2float(h2) * i2, __high2float(h3) * i3);
        float* base = outn + (size_t)(2 * cp) * H * W + p0 + pl;
        *reinterpret_cast<float4*>(base)         = lo;
        *reinterpret_cast<float4*>(base + H * W) = hi;
    }
    if (threadIdx.x < TP) {
        float h = __uint_as_float(tile[threadIdx.x * SPAD + (C >> 1) + 1]);
        float r = h / (h + EPSV);
        bm[(size_t)gp0 + threadIdx.x] = (r <= 0.5f) ? 1.f : 0.f;
    }
}

__device__ __forceinline__ void norm_flow_body(
    int i, const float* __restrict__ acc, float* __restrict__ ft2)
{
    float4 a = *reinterpret_cast<const float4*>(acc + (size_t)i * SF);
    float inv = 1.f / (a.z + EPSV);
    int n = i / HW0;
    int p = i % HW0;
    float* dst = ft2 + (size_t)n * 2 * HW0;
    dst[p]       = -a.x * inv;
    dst[HW0 + p] = -a.y * inv;
}

// ---- ALL normalization in one launch (union smem, largest segment first) ----
#define NBLK_N0 (NB*HW0/64)    // 7168  (TP=64)
#define NBLK_NF (NB*HW0/256)   // 1792
#define NBLK_N1 (NB*HW1/64)    // 1792  (TP=64)
#define NBLK_N2 (NB*HW2/32)    // 896   (TP=32)
#define NBLK_NORM (NBLK_N0+NBLK_NF+NBLK_N1+NBLK_N2)

// union smem: max(64*(S0+1), 64*(S1+1), 32*(S2+1)) = max(1344,2368,1696) = 2368
#define TILE_MAX 2368

__global__ __launch_bounds__(256) void norm_fused_kernel(
    const unsigned* __restrict__ acc0, const unsigned* __restrict__ acc1,
    const unsigned* __restrict__ acc2, const float* __restrict__ accF,
    float* __restrict__ w0, float* __restrict__ w1, float* __restrict__ w2,
    float* __restrict__ bm0, float* __restrict__ bm1, float* __restrict__ bm2,
    float* __restrict__ ft2)
{
    __shared__ unsigned tile[TILE_MAX];
    __shared__ float inv[64];
    int b = blockIdx.x;
    if (b < NBLK_N0) {
        norm_level_body<C0, H0, W0, S0, 64>(b, acc0, w0, bm0, tile, inv);
    } else if (b < NBLK_N0 + NBLK_NF) {
        int i = (b - NBLK_N0) * 256 + threadIdx.x;
        norm_flow_body(i, accF, ft2);
    } else if (b < NBLK_N0 + NBLK_NF + NBLK_N1) {
        norm_level_body<C1, H1, W1, S1, 64>(b - NBLK_N0 - NBLK_NF,
                                            acc1, w1, bm1, tile, inv);
    } else {
        norm_level_body<C2, H2, W2, S2, 32>(b - NBLK_N0 - NBLK_NF - NBLK_N1,
                                            acc2, w2, bm2, tile, inv);
    }
}

extern "C" void kernel_launch(void* const* d_in, const int* in_sizes, int n_in,
                              void* d_out, int out_size)
{
    // metadata order: 0:x1_0 1:x2_0 2:x1_1 3:x2_1 4:x1_2 5:x2_2 6:m1t 7:m2t 8:F12 9:F21
    const float* x1_0 = (const float*)d_in[0];
    const float* x1_1 = (const float*)d_in[2];
    const float* x1_2 = (const float*)d_in[4];
    const float* m1t = (const float*)d_in[6];
    const float* m2t = (const float*)d_in[7];
    const float* F12 = (const float*)d_in[8];
    const float* F21 = (const float*)d_in[9];

    float* out = (float*)d_out;
    float* w0  = out;
    float* w1  = w0 + (size_t)NB * C0 * HW0;
    float* w2  = w1 + (size_t)NB * C1 * HW1;
    float* bm0 = w2 + (size_t)NB * C2 * HW2;
    float* bm1 = bm0 + (size_t)NB * HW0;
    float* bm2 = bm1 + (size_t)NB * HW1;
    float* ft2 = bm2 + (size_t)NB * HW2;

    unsigned* scratch = nullptr;
    cudaGetSymbolAddress((void**)&scratch, g_scratch);
    unsigned* acc0 = scratch + OFF_ACC0;
    unsigned* acc1 = scratch + OFF_ACC1;
    unsigned* acc2 = scratch + OFF_ACC2;
    float* accF  = reinterpret_cast<float*>(scratch + OFF_ACCF);
    float* flow1 = reinterpret_cast<float*>(scratch + OFF_FLOW1);
    float* met1  = reinterpret_cast<float*>(scratch + OFF_MET1);
    float* flow2 = reinterpret_cast<float*>(scratch + OFF_FLOW2);
    float* met2  = reinterpret_cast<float*>(scratch + OFF_MET2);

    const int TB = 256;

    // resize level1 + zero the accumulators, one launch (independent work)
    resize1_zero_kernel<<<NBLK_R1 + NBLK_Z, TB>>>(
        F12, m1t, flow1, met1, scratch);

    // chained resize level2 (two-pass: exploits level-1 reuse; composition
    // tested in r14 and was 4x redundant work -> rejected)
    {
        int total = NB * 3 * HW2;
        resize2_kernel<<<(total + TB - 1) / TB, TB>>>(
            flow1, met1, flow2, met2);
    }

    // all splats in one launch (largest segment first for wave packing)
    splat_fused_kernel<<<NBLK_SPLAT, TB>>>(
        x1_0, x1_1, x1_2, m1t, m2t, F12, F21,
        flow1, met1, flow2, met2, acc0, acc1, acc2, accF);

    // ALL normalization in one launch
    norm_fused_kernel<<<NBLK_NORM, TB>>>(
        acc0, acc1, acc2, accF, w0, w1, w2, bm0, bm1, bm2, ft2);
}

// round 16
// speedup vs baseline: 1.1040x; 1.0089x over previous
#include <cuda_runtime.h>
#include <cuda_fp16.h>
#include <math.h>

#define EPSV 1e-7f

// ---- problem sizes (fixed by the dataset) ----
#define NB 4
#define H0 256
#define W0 448
#define HW0 (H0*W0)      // 114688
#define H1 128
#define W1 224
#define HW1 (H1*W1)      // 28672
#define H2 64
#define W2 112
#define HW2 (H2*W2)      // 7168
#define C0 32
#define C1 64
#define C2 96

// NHWC accumulator pixel strides in u32 units:
//   [0 .. C/2)  : C channels as f16x2
//   [C/2]       : den  (f32)
//   [C/2+1]     : hole (f32)
//   padded to a multiple of 4 u32 (16B) for v4 RED alignment
#define S0 20
#define S1 36
#define S2 52
#define SF 4             // flow acc: 4 f32 (vx, vy, den, pad)

// ---- scratch layout (u32 units) ----
#define OFF_ACC0  0
#define OFF_ACC1  (OFF_ACC0 + NB*HW0*S0)
#define OFF_ACC2  (OFF_ACC1 + NB*HW1*S1)
#define OFF_ACCF  (OFF_ACC2 + NB*HW2*S2)
#define OFF_FLOW1 (OFF_ACCF + NB*HW0*SF)
#define OFF_MET1  (OFF_FLOW1 + NB*2*HW1)
#define OFF_FLOW2 (OFF_MET1 + NB*HW1)
#define OFF_MET2  (OFF_FLOW2 + NB*2*HW2)
#define SCRATCH_TOTAL (OFF_MET2 + NB*HW2)
#define ACC_TOTAL OFF_FLOW1

__device__ __align__(256) unsigned g_scratch[SCRATCH_TOTAL];

__device__ __forceinline__ void red_add_v4_f32(float* p, float a, float b, float c, float d) {
    asm volatile("red.global.add.v4.f32 [%0], {%1,%2,%3,%4};"
                 :: "l"(p), "f"(a), "f"(b), "f"(c), "f"(d) : "memory");
}
__device__ __forceinline__ void red_add_v2_f32(float* p, float a, float b) {
    asm volatile("red.global.add.v2.f32 [%0], {%1,%2};"
                 :: "l"(p), "f"(a), "f"(b) : "memory");
}
__device__ __forceinline__ void red_add_v4_h2(unsigned* p, unsigned a, unsigned b,
                                              unsigned c, unsigned d) {
    asm volatile("red.global.add.noftz.v4.f16x2 [%0], {%1,%2,%3,%4};"
                 :: "l"(p), "r"(a), "r"(b), "r"(c), "r"(d) : "memory");
}
__device__ __forceinline__ unsigned pack_h2(float lo, float hi) {
    __half2 h = __floats2half2_rn(lo, hi);
    return *reinterpret_cast<unsigned*>(&h);
}

// ---- 2x antialiased bilinear downsample body ----
template<int Hi, int Wi>
__device__ __forceinline__ void resize_body(
    int i,
    const float* __restrict__ src_flow,
    const float* __restrict__ src_met,
    float* __restrict__ dst_flow,
    float* __restrict__ dst_met,
    float flow_scale)
{
    const int Ho = Hi / 2, Wo = Wi / 2;
    int total = NB * 3 * Ho * Wo;
    if (i >= total) return;
    int p  = i % (Ho * Wo);
    int nc = i / (Ho * Wo);
    int c  = nc % 3;
    int n  = nc / 3;
    int oy = p / Wo, ox = p % Wo;

    const float raw[4] = {0.25f, 0.75f, 0.75f, 0.25f};
    float wy[4], wx[4];
    int   jy[4], jx[4];
    float sy = 0.f, sx = 0.f;
#pragma unroll
    for (int k = 0; k < 4; k++) {
        int j = 2 * oy - 1 + k;
        float w = (j >= 0 && j < Hi) ? raw[k] : 0.f;
        jy[k] = min(max(j, 0), Hi - 1);
        wy[k] = w; sy += w;
    }
#pragma unroll
    for (int k = 0; k < 4; k++) {
        int j = 2 * ox - 1 + k;
        float w = (j >= 0 && j < Wi) ? raw[k] : 0.f;
        jx[k] = min(max(j, 0), Wi - 1);
        wx[k] = w; sx += w;
    }
    float inv = 1.f / (sy * sx);

    const float* src = (c < 2) ? (src_flow + ((size_t)n * 2 + c) * Hi * Wi)
                               : (src_met  + (size_t)n * Hi * Wi);
    float acc = 0.f;
#pragma unroll
    for (int ky = 0; ky < 4; ky++) {
        if (wy[ky] == 0.f) continue;
        const float* row = src + (size_t)jy[ky] * Wi;
        float a = 0.f;
#pragma unroll
        for (int kx = 0; kx < 4; kx++) a += wx[kx] * row[jx[kx]];
        acc += wy[ky] * a;
    }
    acc *= inv;

    if (c < 2) dst_flow[((size_t)n * 2 + c) * Ho * Wo + p] = acc * flow_scale;
    else       dst_met [(size_t)n * Ho * Wo + p] = acc;
}

// ---- resize level1 + accumulator zeroing fused into ONE launch ----
#define NBLK_R1 ((NB*3*HW1 + 255) / 256)    // 1344
#define NBLK_Z  2048
#define NVEC_ACC (ACC_TOTAL / 4)            // uint4 count (ACC_TOTAL % 4 == 0)

__global__ __launch_bounds__(256) void resize1_zero_kernel(
    const float* __restrict__ F12,
    const float* __restrict__ m1t,
    float* __restrict__ dst_flow,
    float* __restrict__ dst_met,
    unsigned* __restrict__ scratch)
{
    int b = blockIdx.x;
    if (b < NBLK_R1) {
        resize_body<H0, W0>(b * 256 + threadIdx.x, F12, m1t,
                            dst_flow, dst_met, 0.25f);
    } else {
        uint4* dst = reinterpret_cast<uint4*>(scratch);
        const uint4 z = make_uint4(0u, 0u, 0u, 0u);
        int tid = (b - NBLK_R1) * 256 + threadIdx.x;
        const int stride = NBLK_Z * 256;
        for (int j = tid; j < NVEC_ACC; j += stride) dst[j] = z;
    }
}

__global__ __launch_bounds__(256) void resize2_kernel(
    const float* __restrict__ src_flow,
    const float* __restrict__ src_met,
    float* __restrict__ dst_flow,
    float* __restrict__ dst_met)
{
    resize_body<H1, W1>(blockIdx.x * 256 + threadIdx.x, src_flow, src_met,
                        dst_flow, dst_met, 0.5f);
}

// ---- splat bodies: 8 channels per thread (lower regs -> higher occupancy) ----
template<int C, int H, int W, int SP>
__device__ __forceinline__ void splat_level_body(
    int i,
    const float* __restrict__ feat,
    const float* __restrict__ flow,
    const float* __restrict__ metric,
    unsigned* __restrict__ acc,
    float flow_scale)
{
    constexpr int P = NB * H * W;
    int pix = i % P;
    int g   = i / P;          // channel group, 8 channels each
    int n = pix / (H * W);
    int p = pix % (H * W);
    int y = p / W, x = p % W;

    const float* fl = flow + (size_t)n * 2 * H * W;
    float gx = (float)x + fl[p]         * flow_scale;
    float gy = (float)y + fl[H * W + p] * flow_scale;
    float x0f = floorf(gx), y0f = floorf(gy);
    float fx = gx - x0f, fy = gy - y0f;
    int x0 = (int)x0f, y0 = (int)y0f;

    float m = metric[(size_t)n * H * W + p];
    float e = __expf(fminf(fmaxf(-m, -20.f), 20.f));

    float w[4]  = {(1.f - fx) * (1.f - fy), fx * (1.f - fy),
                   (1.f - fx) * fy,         fx * fy};
    int   xi[2] = {x0, x0 + 1};
    int   yi[2] = {y0, y0 + 1};
    bool  vx[2] = {x0 >= 0 && x0 < W, x0 + 1 >= 0 && x0 + 1 < W};
    bool  vy[2] = {y0 >= 0 && y0 < H, y0 + 1 >= 0 && y0 + 1 < H};

    int c0 = g * 8;
    const float* fp = feat + (size_t)n * C * H * W + (size_t)c0 * H * W + p;
    float v[8];
#pragma unroll
    for (int j = 0; j < 8; j++) v[j] = fp[(size_t)j * H * W] * e;

#pragma unroll
    for (int ky = 0; ky < 2; ky++) {
#pragma unroll
        for (int kx = 0; kx < 2; kx++) {
            if (!(vx[kx] && vy[ky])) continue;
            float wk = w[ky * 2 + kx];
            unsigned* pixbase = acc + ((size_t)n * H * W + yi[ky] * W + xi[kx]) * SP;
            unsigned pk0 = pack_h2(wk * v[0], wk * v[1]);
            unsigned pk1 = pack_h2(wk * v[2], wk * v[3]);
            unsigned pk2 = pack_h2(wk * v[4], wk * v[5]);
            unsigned pk3 = pack_h2(wk * v[6], wk * v[7]);
            red_add_v4_h2(pixbase + (c0 >> 1), pk0, pk1, pk2, pk3);
            if (g == 0)
                red_add_v2_f32(reinterpret_cast<float*>(pixbase + (C >> 1)),
                               wk * e, wk);
        }
    }
}

__device__ __forceinline__ void splat_flow_body(
    int i,
    const float* __restrict__ F21,
    const float* __restrict__ m2t,
    float* __restrict__ acc)
{
    constexpr int H = H0, W = W0;
    int n = i / (H * W);
    int p = i % (H * W);
    int y = p / W, x = p % W;

    const float* fl = F21 + (size_t)n * 2 * H * W;
    float ux = fl[p] * 0.5f;
    float uy = fl[H * W + p] * 0.5f;
    float gx = (float)x + ux;
    float gy = (float)y + uy;
    float x0f = floorf(gx), y0f = floorf(gy);
    float fx = gx - x0f, fy = gy - y0f;
    int x0 = (int)x0f, y0 = (int)y0f;

    float m = m2t[(size_t)n * H * W + p];
    float e = __expf(fminf(fmaxf(-m, -20.f), 20.f));
    float vx0 = ux * e, vy0 = uy * e;

    float w[4]  = {(1.f - fx) * (1.f - fy), fx * (1.f - fy),
                   (1.f - fx) * fy,         fx * fy};
    int   xi[2] = {x0, x0 + 1};
    int   yi[2] = {y0, y0 + 1};
    bool  bx[2] = {x0 >= 0 && x0 < W, x0 + 1 >= 0 && x0 + 1 < W};
    bool  by[2] = {y0 >= 0 && y0 < H, y0 + 1 >= 0 && y0 + 1 < H};

#pragma unroll
    for (int ky = 0; ky < 2; ky++) {
#pragma unroll
        for (int kx = 0; kx < 2; kx++) {
            if (!(bx[kx] && by[ky])) continue;
            float wk = w[ky * 2 + kx];
            float* base = acc + ((size_t)n * H * W + yi[ky] * W + xi[kx]) * SF;
            red_add_v4_f32(base, wk * vx0, wk * vy0, wk * e, 0.f);
        }
    }
}

// ---- one fused splat kernel: block-range dispatch (largest first) ----
#define NBLK_S0 (NB*HW0*(C0/8)/256)    // 7168
#define NBLK_SF (NB*HW0/256)           // 1792
#define NBLK_S1 (NB*HW1*(C1/8)/256)    // 3584
#define NBLK_S2 (NB*HW2*(C2/8)/256)    // 1344
#define NBLK_SPLAT (NBLK_S0+NBLK_SF+NBLK_S1+NBLK_S2)

__global__ __launch_bounds__(256) void splat_fused_kernel(
    const float* __restrict__ x1_0, const float* __restrict__ x1_1,
    const float* __restrict__ x1_2,
    const float* __restrict__ m1t,  const float* __restrict__ m2t,
    const float* __restrict__ F12,  const float* __restrict__ F21,
    const float* __restrict__ flow1, const float* __restrict__ met1,
    const float* __restrict__ flow2, const float* __restrict__ met2,
    unsigned* __restrict__ acc0, unsigned* __restrict__ acc1,
    unsigned* __restrict__ acc2, float* __restrict__ accF)
{
    int b = blockIdx.x;
    if (b < NBLK_S0) {
        int i = b * 256 + threadIdx.x;
        splat_level_body<C0, H0, W0, S0>(i, x1_0, F12, m1t, acc0, 0.5f);
    } else if (b < NBLK_S0 + NBLK_SF) {
        int i = (b - NBLK_S0) * 256 + threadIdx.x;
        splat_flow_body(i, F21, m2t, accF);
    } else if (b < NBLK_S0 + NBLK_SF + NBLK_S1) {
        int i = (b - NBLK_S0 - NBLK_SF) * 256 + threadIdx.x;
        splat_level_body<C1, H1, W1, S1>(i, x1_1, flow1, met1, acc1, 1.0f);
    } else {
        int i = (b - NBLK_S0 - NBLK_SF - NBLK_S1) * 256 + threadIdx.x;
        splat_level_body<C2, H2, W2, S2>(i, x1_2, flow2, met2, acc2, 1.0f);
    }
}

// ---- norm bodies (smem provided by caller; sized for the largest user) ----
template<int C, int H, int W, int SP, int TP>
__device__ __forceinline__ void norm_level_body(
    int blk,
    const unsigned* __restrict__ acc,
    float* __restrict__ out,
    float* __restrict__ bm,
    unsigned* tile, float* inv)
{
    constexpr int SPAD = SP + 1;
    int gp0 = blk * TP;
    const uint4* src4 = reinterpret_cast<const uint4*>(acc + (size_t)gp0 * SP);
    constexpr int NV = TP * SP / 4;
    for (int j4 = threadIdx.x; j4 < NV; j4 += 256) {
        uint4 val = src4[j4];
        int j  = j4 * 4;
        int pl = j / SP;
        int k  = j - pl * SP;
        unsigned* t = tile + pl * SPAD + k;
        t[0] = val.x; t[1] = val.y; t[2] = val.z; t[3] = val.w;
    }
    __syncthreads();
    if (threadIdx.x < TP)
        inv[threadIdx.x] =
            1.f / (__uint_as_float(tile[threadIdx.x * SPAD + (C >> 1)]) + EPSV);
    __syncthreads();

    int n  = gp0 / (H * W);
    int p0 = gp0 % (H * W);
    float* outn = out + (size_t)n * C * H * W;
    constexpr int NQ = TP / 4;
    constexpr int NOUT = (C / 2) * NQ;
    for (int j = threadIdx.x; j < NOUT; j += 256) {
        int q  = j % NQ;
        int cp = j / NQ;
        int pl = 4 * q;
        unsigned u0 = tile[(pl + 0) * SPAD + cp];
        unsigned u1 = tile[(pl + 1) * SPAD + cp];
        unsigned u2 = tile[(pl + 2) * SPAD + cp];
        unsigned u3 = tile[(pl + 3) * SPAD + cp];
        __half2 h0 = *reinterpret_cast<__half2*>(&u0);
        __half2 h1 = *reinterpret_cast<__half2*>(&u1);
        __half2 h2 = *reinterpret_cast<__half2*>(&u2);
        __half2 h3 = *reinterpret_cast<__half2*>(&u3);
        float i0 = inv[pl], i1 = inv[pl + 1], i2 = inv[pl + 2], i3 = inv[pl + 3];
        float4 lo = make_float4(__low2float(h0) * i0, __low2float(h1) * i1,
                                __low2float(h2) * i2, __low2float(h3) * i3);
        float4 hi = make_float4(__high2float(h0) * i0, __high2float(h1) * i1,
                                __high2float(h2) * i2, __high2float(h3) * i3);
        float* base = outn + (size_t)(2 * cp) * H * W + p0 + pl;
        *reinterpret_cast<float4*>(base)         = lo;
        *reinterpret_cast<float4*>(base + H * W) = hi;
    }
    if (threadIdx.x < TP) {
        float h = __uint_as_float(tile[threadIdx.x * SPAD + (C >> 1) + 1]);
        float r = h / (h + EPSV);
        bm[(size_t)gp0 + threadIdx.x] = (r <= 0.5f) ? 1.f : 0.f;
    }
}

__device__ __forceinline__ void norm_flow_body(
    int i, const float* __restrict__ acc, float* __restrict__ ft2)
{
    float4 a = *reinterpret_cast<const float4*>(acc + (size_t)i * SF);
    float inv = 1.f / (a.z + EPSV);
    int n = i / HW0;
    int p = i % HW0;
    float* dst = ft2 + (size_t)n * 2 * HW0;
    dst[p]       = -a.x * inv;
    dst[HW0 + p] = -a.y * inv;
}

// ---- ALL normalization in one launch (union smem, largest segment first) ----
#define NBLK_N0 (NB*HW0/64)    // 7168  (TP=64)
#define NBLK_NF (NB*HW0/256)   // 1792
#define NBLK_N1 (NB*HW1/64)    // 1792  (TP=64)
#define NBLK_N2 (NB*HW2/32)    // 896   (TP=32)
#define NBLK_NORM (NBLK_N0+NBLK_NF+NBLK_N1+NBLK_N2)

// union smem: max(64*(S0+1), 64*(S1+1), 32*(S2+1)) = 2368
#define TILE_MAX 2368

__global__ __launch_bounds__(256) void norm_fused_kernel(
    const unsigned* __restrict__ acc0, const unsigned* __restrict__ acc1,
    const unsigned* __restrict__ acc2, const float* __restrict__ accF,
    float* __restrict__ w0, float* __restrict__ w1, float* __restrict__ w2,
    float* __restrict__ bm0, float* __restrict__ bm1, float* __restrict__ bm2,
    float* __restrict__ ft2)
{
    __shared__ unsigned tile[TILE_MAX];
    __shared__ float inv[64];
    int b = blockIdx.x;
    if (b < NBLK_N0) {
        norm_level_body<C0, H0, W0, S0, 64>(b, acc0, w0, bm0, tile, inv);
    } else if (b < NBLK_N0 + NBLK_NF) {
        int i = (b - NBLK_N0) * 256 + threadIdx.x;
        norm_flow_body(i, accF, ft2);
    } else if (b < NBLK_N0 + NBLK_NF + NBLK_N1) {
        norm_level_body<C1, H1, W1, S1, 64>(b - NBLK_N0 - NBLK_NF,
                                            acc1, w1, bm1, tile, inv);
    } else {
        norm_level_body<C2, H2, W2, S2, 32>(b - NBLK_N0 - NBLK_NF - NBLK_N1,
                                            acc2, w2, bm2, tile, inv);
    }
}

extern "C" void kernel_launch(void* const* d_in, const int* in_sizes, int n_in,
                              void* d_out, int out_size)
{
    // metadata order: 0:x1_0 1:x2_0 2:x1_1 3:x2_1 4:x1_2 5:x2_2 6:m1t 7:m2t 8:F12 9:F21
    const float* x1_0 = (const float*)d_in[0];
    const float* x1_1 = (const float*)d_in[2];
    const float* x1_2 = (const float*)d_in[4];
    const float* m1t = (const float*)d_in[6];
    const float* m2t = (const float*)d_in[7];
    const float* F12 = (const float*)d_in[8];
    const float* F21 = (const float*)d_in[9];

    float* out = (float*)d_out;
    float* w0  = out;
    float* w1  = w0 + (size_t)NB * C0 * HW0;
    float* w2  = w1 + (size_t)NB * C1 * HW1;
    float* bm0 = w2 + (size_t)NB * C2 * HW2;
    float* bm1 = bm0 + (size_t)NB * HW0;
    float* bm2 = bm1 + (size_t)NB * HW1;
    float* ft2 = bm2 + (size_t)NB * HW2;

    unsigned* scratch = nullptr;
    cudaGetSymbolAddress((void**)&scratch, g_scratch);
    unsigned* acc0 = scratch + OFF_ACC0;
    unsigned* acc1 = scratch + OFF_ACC1;
    unsigned* acc2 = scratch + OFF_ACC2;
    float* accF  = reinterpret_cast<float*>(scratch + OFF_ACCF);
    float* flow1 = reinterpret_cast<float*>(scratch + OFF_FLOW1);
    float* met1  = reinterpret_cast<float*>(scratch + OFF_MET1);
    float* flow2 = reinterpret_cast<float*>(scratch + OFF_FLOW2);
    float* met2  = reinterpret_cast<float*>(scratch + OFF_MET2);

    const int TB = 256;

    // resize level1 + zero the accumulators, one launch (independent work)
    resize1_zero_kernel<<<NBLK_R1 + NBLK_Z, TB>>>(
        F12, m1t, flow1, met1, scratch);

    // chained resize level2
    {
        int total = NB * 3 * HW2;
        resize2_kernel<<<(total + TB - 1) / TB, TB>>>(
            flow1, met1, flow2, met2);
    }

    // all splats in one launch (8 channels/thread for occupancy)
    splat_fused_kernel<<<NBLK_SPLAT, TB>>>(
        x1_0, x1_1, x1_2, m1t, m2t, F12, F21,
        flow1, met1, flow2, met2, acc0, acc1, acc2, accF);

    // ALL normalization in one launch
    norm_fused_kernel<<<NBLK_NORM, TB>>>(
        acc0, acc1, acc2, accF, w0, w1, w2, bm0, bm1, bm2, ft2);
}

// round 17
// speedup vs baseline: 1.1209x; 1.0153x over previous
#include <cuda_runtime.h>
#include <cuda_fp16.h>
#include <math.h>

#define EPSV 1e-7f

// ---- problem sizes (fixed by the dataset) ----
#define NB 4
#define H0 256
#define W0 448
#define HW0 (H0*W0)      // 114688
#define H1 128
#define W1 224
#define HW1 (H1*W1)      // 28672
#define H2 64
#define W2 112
#define HW2 (H2*W2)      // 7168
#define C0 32
#define C1 64
#define C2 96

// NHWC accumulator pixel strides in u32 units:
//   [0 .. C/2)  : C channels as f16x2
//   [C/2]       : den  (f32)
//   [C/2+1]     : hole (f32)
//   padded to a multiple of 4 u32 (16B) for v4 RED alignment
#define S0 20
#define S1 36
#define S2 52
#define SF 4             // flow acc: 4 f32 (vx, vy, den, pad)

// ---- scratch layout (u32 units) ----
#define OFF_ACC0  0
#define OFF_ACC1  (OFF_ACC0 + NB*HW0*S0)
#define OFF_ACC2  (OFF_ACC1 + NB*HW1*S1)
#define OFF_ACCF  (OFF_ACC2 + NB*HW2*S2)
#define OFF_FLOW1 (OFF_ACCF + NB*HW0*SF)
#define OFF_MET1  (OFF_FLOW1 + NB*2*HW1)
#define OFF_FLOW2 (OFF_MET1 + NB*HW1)
#define OFF_MET2  (OFF_FLOW2 + NB*2*HW2)
#define SCRATCH_TOTAL (OFF_MET2 + NB*HW2)
#define ACC_TOTAL OFF_FLOW1

__device__ __align__(256) unsigned g_scratch[SCRATCH_TOTAL];
__device__ unsigned g_r2_done;   // resize2 completion counter (reset by prep)

__device__ __forceinline__ void red_add_v4_f32(float* p, float a, float b, float c, float d) {
    asm volatile("red.global.add.v4.f32 [%0], {%1,%2,%3,%4};"
                 :: "l"(p), "f"(a), "f"(b), "f"(c), "f"(d) : "memory");
}
__device__ __forceinline__ void red_add_v2_f32(float* p, float a, float b) {
    asm volatile("red.global.add.v2.f32 [%0], {%1,%2};"
                 :: "l"(p), "f"(a), "f"(b) : "memory");
}
__device__ __forceinline__ void red_add_v4_h2(unsigned* p, unsigned a, unsigned b,
                                              unsigned c, unsigned d) {
    asm volatile("red.global.add.noftz.v4.f16x2 [%0], {%1,%2,%3,%4};"
                 :: "l"(p), "r"(a), "r"(b), "r"(c), "r"(d) : "memory");
}
__device__ __forceinline__ unsigned pack_h2(float lo, float hi) {
    __half2 h = __floats2half2_rn(lo, hi);
    return *reinterpret_cast<unsigned*>(&h);
}

// ---- 2x antialiased bilinear downsample body ----
template<int Hi, int Wi>
__device__ __forceinline__ void resize_body(
    int i,
    const float* __restrict__ src_flow,
    const float* __restrict__ src_met,
    float* __restrict__ dst_flow,
    float* __restrict__ dst_met,
    float flow_scale)
{
    const int Ho = Hi / 2, Wo = Wi / 2;
    int total = NB * 3 * Ho * Wo;
    if (i >= total) return;
    int p  = i % (Ho * Wo);
    int nc = i / (Ho * Wo);
    int c  = nc % 3;
    int n  = nc / 3;
    int oy = p / Wo, ox = p % Wo;

    const float raw[4] = {0.25f, 0.75f, 0.75f, 0.25f};
    float wy[4], wx[4];
    int   jy[4], jx[4];
    float sy = 0.f, sx = 0.f;
#pragma unroll
    for (int k = 0; k < 4; k++) {
        int j = 2 * oy - 1 + k;
        float w = (j >= 0 && j < Hi) ? raw[k] : 0.f;
        jy[k] = min(max(j, 0), Hi - 1);
        wy[k] = w; sy += w;
    }
#pragma unroll
    for (int k = 0; k < 4; k++) {
        int j = 2 * ox - 1 + k;
        float w = (j >= 0 && j < Wi) ? raw[k] : 0.f;
        jx[k] = min(max(j, 0), Wi - 1);
        wx[k] = w; sx += w;
    }
    float inv = 1.f / (sy * sx);

    const float* src = (c < 2) ? (src_flow + ((size_t)n * 2 + c) * Hi * Wi)
                               : (src_met  + (size_t)n * Hi * Wi);
    float acc = 0.f;
#pragma unroll
    for (int ky = 0; ky < 4; ky++) {
        if (wy[ky] == 0.f) continue;
        const float* row = src + (size_t)jy[ky] * Wi;
        float a = 0.f;
#pragma unroll
        for (int kx = 0; kx < 4; kx++) a += wx[kx] * row[jx[kx]];
        acc += wy[ky] * a;
    }
    acc *= inv;

    if (c < 2) dst_flow[((size_t)n * 2 + c) * Ho * Wo + p] = acc * flow_scale;
    else       dst_met [(size_t)n * Ho * Wo + p] = acc;
}

// ---- prep: resize level1 + accumulator zeroing + counter reset ----
#define NBLK_R1 ((NB*3*HW1 + 255) / 256)    // 1344
#define NBLK_Z  2048
#define NVEC_ACC (ACC_TOTAL / 4)

__global__ __launch_bounds__(256) void resize1_zero_kernel(
    const float* __restrict__ F12,
    const float* __restrict__ m1t,
    float* __restrict__ dst_flow,
    float* __restrict__ dst_met,
    unsigned* __restrict__ scratch)
{
    int b = blockIdx.x;
    if (b < NBLK_R1) {
        resize_body<H0, W0>(b * 256 + threadIdx.x, F12, m1t,
                            dst_flow, dst_met, 0.25f);
    } else {
        if (b == NBLK_R1 && threadIdx.x == 0) g_r2_done = 0;  // reset gate
        uint4* dst = reinterpret_cast<uint4*>(scratch);
        const uint4 z = make_uint4(0u, 0u, 0u, 0u);
        int tid = (b - NBLK_R1) * 256 + threadIdx.x;
        const int stride = NBLK_Z * 256;
        for (int j = tid; j < NVEC_ACC; j += stride) dst[j] = z;
    }
}

// ---- splat bodies: 8 channels per thread ----
template<int C, int H, int W, int SP>
__device__ __forceinline__ void splat_level_body(
    int i,
    const float* __restrict__ feat,
    const float* __restrict__ flow,
    const float* __restrict__ metric,
    unsigned* __restrict__ acc,
    float flow_scale)
{
    constexpr int P = NB * H * W;
    int pix = i % P;
    int g   = i / P;
    int n = pix / (H * W);
    int p = pix % (H * W);
    int y = p / W, x = p % W;

    const float* fl = flow + (size_t)n * 2 * H * W;
    float gx = (float)x + fl[p]         * flow_scale;
    float gy = (float)y + fl[H * W + p] * flow_scale;
    float x0f = floorf(gx), y0f = floorf(gy);
    float fx = gx - x0f, fy = gy - y0f;
    int x0 = (int)x0f, y0 = (int)y0f;

    float m = metric[(size_t)n * H * W + p];
    float e = __expf(fminf(fmaxf(-m, -20.f), 20.f));

    float w[4]  = {(1.f - fx) * (1.f - fy), fx * (1.f - fy),
                   (1.f - fx) * fy,         fx * fy};
    int   xi[2] = {x0, x0 + 1};
    int   yi[2] = {y0, y0 + 1};
    bool  vx[2] = {x0 >= 0 && x0 < W, x0 + 1 >= 0 && x0 + 1 < W};
    bool  vy[2] = {y0 >= 0 && y0 < H, y0 + 1 >= 0 && y0 + 1 < H};

    int c0 = g * 8;
    const float* fp = feat + (size_t)n * C * H * W + (size_t)c0 * H * W + p;
    float v[8];
#pragma unroll
    for (int j = 0; j < 8; j++) v[j] = fp[(size_t)j * H * W] * e;

#pragma unroll
    for (int ky = 0; ky < 2; ky++) {
#pragma unroll
        for (int kx = 0; kx < 2; kx++) {
            if (!(vx[kx] && vy[ky])) continue;
            float wk = w[ky * 2 + kx];
            unsigned* pixbase = acc + ((size_t)n * H * W + yi[ky] * W + xi[kx]) * SP;
            unsigned pk0 = pack_h2(wk * v[0], wk * v[1]);
            unsigned pk1 = pack_h2(wk * v[2], wk * v[3]);
            unsigned pk2 = pack_h2(wk * v[4], wk * v[5]);
            unsigned pk3 = pack_h2(wk * v[6], wk * v[7]);
            red_add_v4_h2(pixbase + (c0 >> 1), pk0, pk1, pk2, pk3);
            if (g == 0)
                red_add_v2_f32(reinterpret_cast<float*>(pixbase + (C >> 1)),
                               wk * e, wk);
        }
    }
}

__device__ __forceinline__ void splat_flow_body(
    int i,
    const float* __restrict__ F21,
    const float* __restrict__ m2t,
    float* __restrict__ acc)
{
    constexpr int H = H0, W = W0;
    int n = i / (H * W);
    int p = i % (H * W);
    int y = p / W, x = p % W;

    const float* fl = F21 + (size_t)n * 2 * H * W;
    float ux = fl[p] * 0.5f;
    float uy = fl[H * W + p] * 0.5f;
    float gx = (float)x + ux;
    float gy = (float)y + uy;
    float x0f = floorf(gx), y0f = floorf(gy);
    float fx = gx - x0f, fy = gy - y0f;
    int x0 = (int)x0f, y0 = (int)y0f;

    float m = m2t[(size_t)n * H * W + p];
    float e = __expf(fminf(fmaxf(-m, -20.f), 20.f));
    float vx0 = ux * e, vy0 = uy * e;

    float w[4]  = {(1.f - fx) * (1.f - fy), fx * (1.f - fy),
                   (1.f - fx) * fy,         fx * fy};
    int   xi[2] = {x0, x0 + 1};
    int   yi[2] = {y0, y0 + 1};
    bool  bx[2] = {x0 >= 0 && x0 < W, x0 + 1 >= 0 && x0 + 1 < W};
    bool  by[2] = {y0 >= 0 && y0 < H, y0 + 1 >= 0 && y0 + 1 < H};

#pragma unroll
    for (int ky = 0; ky < 2; ky++) {
#pragma unroll
        for (int kx = 0; kx < 2; kx++) {
            if (!(bx[kx] && by[ky])) continue;
            float wk = w[ky * 2 + kx];
            float* base = acc + ((size_t)n * H * W + yi[ky] * W + xi[kx]) * SF;
            red_add_v4_f32(base, wk * vx0, wk * vy0, wk * e, 0.f);
        }
    }
}

// ---- one fused splat kernel with embedded resize2 + dependency gate ----
// Block order: [resize2 | splat L0 | splat flow | splat L1 | splat L2(gated)]
// resize2 blocks come FIRST (CTAs dispatch in increasing blockIdx order), so
// the gated L2 blocks (last ~1.3K of 14.2K) can never be resident before the
// 336 producer blocks have been dispatched -> spin cannot deadlock.
#define NBLK_R2 ((NB*3*HW2 + 255) / 256)        // 336
#define NBLK_S0 (NB*HW0*(C0/8)/256)             // 7168
#define NBLK_SF (NB*HW0/256)                    // 1792
#define NBLK_S1 (NB*HW1*(C1/8)/256)             // 3584
#define NBLK_S2 (NB*HW2*(C2/8)/256)             // 1344
#define NBLK_SPLAT (NBLK_R2+NBLK_S0+NBLK_SF+NBLK_S1+NBLK_S2)

__global__ __launch_bounds__(256) void splat_fused_kernel(
    const float* __restrict__ x1_0, const float* __restrict__ x1_1,
    const float* __restrict__ x1_2,
    const float* __restrict__ m1t,  const float* __restrict__ m2t,
    const float* __restrict__ F12,  const float* __restrict__ F21,
    const float* __restrict__ flow1, const float* __restrict__ met1,
    float* __restrict__ flow2, float* __restrict__ met2,
    unsigned* __restrict__ acc0, unsigned* __restrict__ acc1,
    unsigned* __restrict__ acc2, float* __restrict__ accF)
{
    int b = blockIdx.x;
    if (b < NBLK_R2) {
        // producer: level-2 resize (flow1/met1 -> flow2/met2)
        resize_body<H1, W1>(b * 256 + threadIdx.x, flow1, met1,
                            flow2, met2, 0.5f);
        __threadfence();            // publish flow2/met2 device-wide
        __syncthreads();
        if (threadIdx.x == 0) atomicAdd(&g_r2_done, 1u);
    } else if (b < NBLK_R2 + NBLK_S0) {
        int i = (b - NBLK_R2) * 256 + threadIdx.x;
        splat_level_body<C0, H0, W0, S0>(i, x1_0, F12, m1t, acc0, 0.5f);
    } else if (b < NBLK_R2 + NBLK_S0 + NBLK_SF) {
        int i = (b - NBLK_R2 - NBLK_S0) * 256 + threadIdx.x;
        splat_flow_body(i, F21, m2t, accF);
    } else if (b < NBLK_R2 + NBLK_S0 + NBLK_SF + NBLK_S1) {
        int i = (b - NBLK_R2 - NBLK_S0 - NBLK_SF) * 256 + threadIdx.x;
        splat_level_body<C1, H1, W1, S1>(i, x1_1, flow1, met1, acc1, 1.0f);
    } else {
        // consumer: wait for resize2 completion (gate), then splat level 2
        if (threadIdx.x == 0) {
            while (*((volatile unsigned*)&g_r2_done) < (unsigned)NBLK_R2) { }
        }
        __syncthreads();            // exec + compiler barrier (no load hoist)
        int i = (b - NBLK_R2 - NBLK_S0 - NBLK_SF - NBLK_S1) * 256 + threadIdx.x;
        splat_level_body<C2, H2, W2, S2>(i, x1_2, flow2, met2, acc2, 1.0f);
    }
}

// ---- norm bodies (smem provided by caller; sized for the largest user) ----
template<int C, int H, int W, int SP, int TP>
__device__ __forceinline__ void norm_level_body(
    int blk,
    const unsigned* __restrict__ acc,
    float* __restrict__ out,
    float* __restrict__ bm,
    unsigned* tile, float* inv)
{
    constexpr int SPAD = SP + 1;
    int gp0 = blk * TP;
    const uint4* src4 = reinterpret_cast<const uint4*>(acc + (size_t)gp0 * SP);
    constexpr int NV = TP * SP / 4;
    for (int j4 = threadIdx.x; j4 < NV; j4 += 256) {
        uint4 val = src4[j4];
        int j  = j4 * 4;
        int pl = j / SP;
        int k  = j - pl * SP;
        unsigned* t = tile + pl * SPAD + k;
        t[0] = val.x; t[1] = val.y; t[2] = val.z; t[3] = val.w;
    }
    __syncthreads();
    if (threadIdx.x < TP)
        inv[threadIdx.x] =
            1.f / (__uint_as_float(tile[threadIdx.x * SPAD + (C >> 1)]) + EPSV);
    __syncthreads();

    int n  = gp0 / (H * W);
    int p0 = gp0 % (H * W);
    float* outn = out + (size_t)n * C * H * W;
    constexpr int NQ = TP / 4;
    constexpr int NOUT = (C / 2) * NQ;
    for (int j = threadIdx.x; j < NOUT; j += 256) {
        int q  = j % NQ;
        int cp = j / NQ;
        int pl = 4 * q;
        unsigned u0 = tile[(pl + 0) * SPAD + cp];
        unsigned u1 = tile[(pl + 1) * SPAD + cp];
        unsigned u2 = tile[(pl + 2) * SPAD + cp];
        unsigned u3 = tile[(pl + 3) * SPAD + cp];
        __half2 h0 = *reinterpret_cast<__half2*>(&u0);
        __half2 h1 = *reinterpret_cast<__half2*>(&u1);
        __half2 h2 = *reinterpret_cast<__half2*>(&u2);
        __half2 h3 = *reinterpret_cast<__half2*>(&u3);
        float i0 = inv[pl], i1 = inv[pl + 1], i2 = inv[pl + 2], i3 = inv[pl + 3];
        float4 lo = make_float4(__low2float(h0) * i0, __low2float(h1) * i1,
                                __low2float(h2) * i2, __low2float(h3) * i3);
        float4 hi = make_float4(__high2float(h0) * i0, __high2float(h1) * i1,
                                __high2float(h2) * i2, __high2float(h3) * i3);
        float* base = outn + (size_t)(2 * cp) * H * W + p0 + pl;
        *reinterpret_cast<float4*>(base)         = lo;
        *reinterpret_cast<float4*>(base + H * W) = hi;
    }
    if (threadIdx.x < TP) {
        float h = __uint_as_float(tile[threadIdx.x * SPAD + (C >> 1) + 1]);
        float r = h / (h + EPSV);
        bm[(size_t)gp0 + threadIdx.x] = (r <= 0.5f) ? 1.f : 0.f;
    }
}

__device__ __forceinline__ void norm_flow_body(
    int i, const float* __restrict__ acc, float* __restrict__ ft2)
{
    float4 a = *reinterpret_cast<const float4*>(acc + (size_t)i * SF);
    float inv = 1.f / (a.z + EPSV);
    int n = i / HW0;
    int p = i % HW0;
    float* dst = ft2 + (size_t)n * 2 * HW0;
    dst[p]       = -a.x * inv;
    dst[HW0 + p] = -a.y * inv;
}

// ---- ALL normalization in one launch (union smem, largest segment first) ----
#define NBLK_N0 (NB*HW0/64)    // 7168  (TP=64)
#define NBLK_NF (NB*HW0/256)   // 1792
#define NBLK_N1 (NB*HW1/64)    // 1792  (TP=64)
#define NBLK_N2 (NB*HW2/32)    // 896   (TP=32)
#define NBLK_NORM (NBLK_N0+NBLK_NF+NBLK_N1+NBLK_N2)

// union smem: max(64*(S0+1), 64*(S1+1), 32*(S2+1)) = 2368
#define TILE_MAX 2368

__global__ __launch_bounds__(256) void norm_fused_kernel(
    const unsigned* __restrict__ acc0, const unsigned* __restrict__ acc1,
    const unsigned* __restrict__ acc2, const float* __restrict__ accF,
    float* __restrict__ w0, float* __restrict__ w1, float* __restrict__ w2,
    float* __restrict__ bm0, float* __restrict__ bm1, float* __restrict__ bm2,
    float* __restrict__ ft2)
{
    __shared__ unsigned tile[TILE_MAX];
    __shared__ float inv[64];
    int b = blockIdx.x;
    if (b < NBLK_N0) {
        norm_level_body<C0, H0, W0, S0, 64>(b, acc0, w0, bm0, tile, inv);
    } else if (b < NBLK_N0 + NBLK_NF) {
        int i = (b - NBLK_N0) * 256 + threadIdx.x;
        norm_flow_body(i, accF, ft2);
    } else if (b < NBLK_N0 + NBLK_NF + NBLK_N1) {
        norm_level_body<C1, H1, W1, S1, 64>(b - NBLK_N0 - NBLK_NF,
                                            acc1, w1, bm1, tile, inv);
    } else {
        norm_level_body<C2, H2, W2, S2, 32>(b - NBLK_N0 - NBLK_NF - NBLK_N1,
                                            acc2, w2, bm2, tile, inv);
    }
}

extern "C" void kernel_launch(void* const* d_in, const int* in_sizes, int n_in,
                              void* d_out, int out_size)
{
    // metadata order: 0:x1_0 1:x2_0 2:x1_1 3:x2_1 4:x1_2 5:x2_2 6:m1t 7:m2t 8:F12 9:F21
    const float* x1_0 = (const float*)d_in[0];
    const float* x1_1 = (const float*)d_in[2];
    const float* x1_2 = (const float*)d_in[4];
    const float* m1t = (const float*)d_in[6];
    const float* m2t = (const float*)d_in[7];
    const float* F12 = (const float*)d_in[8];
    const float* F21 = (const float*)d_in[9];

    float* out = (float*)d_out;
    float* w0  = out;
    float* w1  = w0 + (size_t)NB * C0 * HW0;
    float* w2  = w1 + (size_t)NB * C1 * HW1;
    float* bm0 = w2 + (size_t)NB * C2 * HW2;
    float* bm1 = bm0 + (size_t)NB * HW0;
    float* bm2 = bm1 + (size_t)NB * HW1;
    float* ft2 = bm2 + (size_t)NB * HW2;

    unsigned* scratch = nullptr;
    cudaGetSymbolAddress((void**)&scratch, g_scratch);
    unsigned* acc0 = scratch + OFF_ACC0;
    unsigned* acc1 = scratch + OFF_ACC1;
    unsigned* acc2 = scratch + OFF_ACC2;
    float* accF  = reinterpret_cast<float*>(scratch + OFF_ACCF);
    float* flow1 = reinterpret_cast<float*>(scratch + OFF_FLOW1);
    float* met1  = reinterpret_cast<float*>(scratch + OFF_MET1);
    float* flow2 = reinterpret_cast<float*>(scratch + OFF_FLOW2);
    float* met2  = reinterpret_cast<float*>(scratch + OFF_MET2);

    const int TB = 256;

    // prep: resize level1 + zero accumulators + reset resize2 gate
    resize1_zero_kernel<<<NBLK_R1 + NBLK_Z, TB>>>(
        F12, m1t, flow1, met1, scratch);

    // splats + embedded resize2 (gated) in one launch
    splat_fused_kernel<<<NBLK_SPLAT, TB>>>(
        x1_0, x1_1, x1_2, m1t, m2t, F12, F21,
        flow1, met1, flow2, met2, acc0, acc1, acc2, accF);

    // ALL normalization in one launch
    norm_fused_kernel<<<NBLK_NORM, TB>>>(
        acc0, acc1, acc2, accF, w0, w1, w2, bm0, bm1, bm2, ft2);
}